// round 1
// baseline (speedup 1.0000x reference)
#include <cuda_runtime.h>

// Problem constants
#define BT_TOK  65536       // B*T tokens
#define D_INV   512         // D_IN
#define D_EMBV  256         // D_EMB
#define K_CODES 1024
#define N_BATCH 16
#define T_SEQ   4096

// Scratch (device globals: no allocation allowed)
__device__ int   g_code[BT_TOK];
__device__ float g_c2[K_CODES];
__device__ float g_loss[N_BATCH];

// ---------------- packed f32x2 helpers (Blackwell dual fp32 pipe) ----------
static __device__ __forceinline__ unsigned long long bcast2(float x) {
    unsigned long long r;
    asm("mov.b64 %0, {%1, %1};" : "=l"(r) : "f"(x));
    return r;
}
static __device__ __forceinline__ void fma2(unsigned long long& c,
                                            unsigned long long a,
                                            unsigned long long b) {
    asm("fma.rn.f32x2 %0, %1, %2, %0;" : "+l"(c) : "l"(a), "l"(b));
}
static __device__ __forceinline__ float2 unpack2(unsigned long long v) {
    float2 f;
    f.x = __uint_as_float((unsigned)(v & 0xffffffffull));
    f.y = __uint_as_float((unsigned)(v >> 32));
    return f;
}

// ---------------- codebook squared norms ------------------------------------
__global__ void k_c2(const float* __restrict__ CB) {
    int k = blockIdx.x * blockDim.x + threadIdx.x;
    if (k < K_CODES) {
        const float* row = CB + k * D_EMBV;
        float s = 0.f;
        #pragma unroll 8
        for (int e = 0; e < D_EMBV; e++) s += row[e] * row[e];
        g_c2[k] = s;
    }
}

__global__ void k_zero() {
    if (threadIdx.x < N_BATCH) g_loss[threadIdx.x] = 0.f;
}

// ---------------- GEMM1: z_e_down = z_e @ W_down^T ---------------------------
// C[BT,256] = A[BT,512] * W[256,512]^T. 64x64x32 tile, 256 thr, 4x4 micro.
__global__ void k_down(const float* __restrict__ A, const float* __restrict__ W,
                       float* __restrict__ C) {
    __shared__ __align__(16) float As[32][68];
    __shared__ __align__(16) float Bs[32][68];
    const int m0 = blockIdx.x * 64;
    const int n0 = blockIdx.y * 64;
    const int tid = threadIdx.x;
    const int tx = tid & 15, ty = tid >> 4;
    unsigned long long acc[4][2];
    #pragma unroll
    for (int i = 0; i < 4; i++) { acc[i][0] = 0ull; acc[i][1] = 0ull; }

    for (int kk = 0; kk < D_INV; kk += 32) {
        #pragma unroll
        for (int i = 0; i < 8; i++) {
            int idx = tid + i * 256;
            int r = idx >> 5, c = idx & 31;
            As[c][r] = A[(m0 + r) * D_INV + kk + c];
            Bs[c][r] = W[(n0 + r) * D_INV + kk + c];
        }
        __syncthreads();
        #pragma unroll
        for (int k = 0; k < 32; k++) {
            float4 av = *(const float4*)&As[k][ty * 4];
            ulonglong2 bv = *(const ulonglong2*)&Bs[k][tx * 4];
            unsigned long long a0 = bcast2(av.x), a1 = bcast2(av.y);
            unsigned long long a2 = bcast2(av.z), a3 = bcast2(av.w);
            fma2(acc[0][0], a0, bv.x); fma2(acc[0][1], a0, bv.y);
            fma2(acc[1][0], a1, bv.x); fma2(acc[1][1], a1, bv.y);
            fma2(acc[2][0], a2, bv.x); fma2(acc[2][1], a2, bv.y);
            fma2(acc[3][0], a3, bv.x); fma2(acc[3][1], a3, bv.y);
        }
        __syncthreads();
    }
    #pragma unroll
    for (int i = 0; i < 4; i++) {
        float2 p0 = unpack2(acc[i][0]), p1 = unpack2(acc[i][1]);
        float4 o = make_float4(p0.x, p0.y, p1.x, p1.y);
        *(float4*)&C[(m0 + ty * 4 + i) * D_EMBV + n0 + tx * 4] = o;
    }
}

// ---------------- distance GEMM + fused argmin --------------------------------
// For each token t: code[t] = argmin_k ( c2[k] - 2 * dot(zed[t], CB[k]) ).
// One block owns 64 tokens and loops over all 1024 codes.
__global__ void k_dist(const float* __restrict__ Z, const float* __restrict__ CB,
                       float* __restrict__ code_f) {
    __shared__ __align__(16) float As[32][68];
    __shared__ __align__(16) float Bs[32][68];
    __shared__ float rv[64][17];
    __shared__ int   ri[64][17];
    const int m0 = blockIdx.x * 64;
    const int tid = threadIdx.x;
    const int tx = tid & 15, ty = tid >> 4;

    float minv[4]; int mini[4];
    #pragma unroll
    for (int i = 0; i < 4; i++) { minv[i] = 3.4e38f; mini[i] = 0; }

    for (int nc = 0; nc < K_CODES / 64; nc++) {
        unsigned long long acc[4][2];
        #pragma unroll
        for (int i = 0; i < 4; i++) { acc[i][0] = 0ull; acc[i][1] = 0ull; }

        for (int kc = 0; kc < D_EMBV / 32; kc++) {
            #pragma unroll
            for (int i = 0; i < 8; i++) {
                int idx = tid + i * 256;
                int r = idx >> 5, c = idx & 31;
                As[c][r] = Z[(m0 + r) * D_EMBV + kc * 32 + c];
                Bs[c][r] = CB[(nc * 64 + r) * D_EMBV + kc * 32 + c];
            }
            __syncthreads();
            #pragma unroll
            for (int k = 0; k < 32; k++) {
                float4 av = *(const float4*)&As[k][ty * 4];
                ulonglong2 bv = *(const ulonglong2*)&Bs[k][tx * 4];
                unsigned long long a0 = bcast2(av.x), a1 = bcast2(av.y);
                unsigned long long a2 = bcast2(av.z), a3 = bcast2(av.w);
                fma2(acc[0][0], a0, bv.x); fma2(acc[0][1], a0, bv.y);
                fma2(acc[1][0], a1, bv.x); fma2(acc[1][1], a1, bv.y);
                fma2(acc[2][0], a2, bv.x); fma2(acc[2][1], a2, bv.y);
                fma2(acc[3][0], a3, bv.x); fma2(acc[3][1], a3, bv.y);
            }
            __syncthreads();
        }
        // distances for this 64-code chunk; update running min (first-index ties)
        int kb = nc * 64 + tx * 4;
        float4 cv = *(const float4*)&g_c2[kb];
        #pragma unroll
        for (int i = 0; i < 4; i++) {
            float2 p0 = unpack2(acc[i][0]), p1 = unpack2(acc[i][1]);
            float d0 = cv.x - 2.f * p0.x;
            float d1 = cv.y - 2.f * p0.y;
            float d2 = cv.z - 2.f * p1.x;
            float d3 = cv.w - 2.f * p1.y;
            if (d0 < minv[i]) { minv[i] = d0; mini[i] = kb;     }
            if (d1 < minv[i]) { minv[i] = d1; mini[i] = kb + 1; }
            if (d2 < minv[i]) { minv[i] = d2; mini[i] = kb + 2; }
            if (d3 < minv[i]) { minv[i] = d3; mini[i] = kb + 3; }
        }
    }
    #pragma unroll
    for (int i = 0; i < 4; i++) {
        rv[ty * 4 + i][tx] = minv[i];
        ri[ty * 4 + i][tx] = mini[i];
    }
    __syncthreads();
    if (tid < 64) {
        float bv = rv[tid][0]; int bi = ri[tid][0];
        #pragma unroll
        for (int x = 1; x < 16; x++) {
            float v = rv[tid][x]; int ix = ri[tid][x];
            if (v < bv || (v == bv && ix < bi)) { bv = v; bi = ix; }
        }
        g_code[m0 + tid] = bi;
        code_f[m0 + tid] = (float)bi;
    }
}

// ---------------- GEMM3: z_q = codebook[code] @ W_up^T -----------------------
// C[BT,512] : C[t,d] = sum_e CB[code[t],e] * Wup[d,e]
__global__ void k_up(const float* __restrict__ CB, const float* __restrict__ W,
                     float* __restrict__ C) {
    __shared__ __align__(16) float As[32][68];
    __shared__ __align__(16) float Bs[32][68];
    __shared__ int codes[64];
    const int m0 = blockIdx.x * 64;
    const int n0 = blockIdx.y * 64;
    const int tid = threadIdx.x;
    const int tx = tid & 15, ty = tid >> 4;
    if (tid < 64) codes[tid] = g_code[m0 + tid];
    __syncthreads();

    unsigned long long acc[4][2];
    #pragma unroll
    for (int i = 0; i < 4; i++) { acc[i][0] = 0ull; acc[i][1] = 0ull; }

    for (int kk = 0; kk < D_EMBV; kk += 32) {
        #pragma unroll
        for (int i = 0; i < 8; i++) {
            int idx = tid + i * 256;
            int r = idx >> 5, c = idx & 31;
            As[c][r] = CB[codes[r] * D_EMBV + kk + c];
            Bs[c][r] = W[(n0 + r) * D_EMBV + kk + c];
        }
        __syncthreads();
        #pragma unroll
        for (int k = 0; k < 32; k++) {
            float4 av = *(const float4*)&As[k][ty * 4];
            ulonglong2 bv = *(const ulonglong2*)&Bs[k][tx * 4];
            unsigned long long a0 = bcast2(av.x), a1 = bcast2(av.y);
            unsigned long long a2 = bcast2(av.z), a3 = bcast2(av.w);
            fma2(acc[0][0], a0, bv.x); fma2(acc[0][1], a0, bv.y);
            fma2(acc[1][0], a1, bv.x); fma2(acc[1][1], a1, bv.y);
            fma2(acc[2][0], a2, bv.x); fma2(acc[2][1], a2, bv.y);
            fma2(acc[3][0], a3, bv.x); fma2(acc[3][1], a3, bv.y);
        }
        __syncthreads();
    }
    #pragma unroll
    for (int i = 0; i < 4; i++) {
        float2 p0 = unpack2(acc[i][0]), p1 = unpack2(acc[i][1]);
        float4 o = make_float4(p0.x, p0.y, p1.x, p1.y);
        *(float4*)&C[(m0 + ty * 4 + i) * D_INV + n0 + tx * 4] = o;
    }
}

// ---------------- per-batch VQ losses ---------------------------------------
// sum over (t,e) of (CB[code[t],e] - zed[t,e])^2, one warp per token.
__global__ void k_loss(const float* __restrict__ Z, const float* __restrict__ CB) {
    int lane = threadIdx.x & 31;
    int t = (blockIdx.x * blockDim.x + threadIdx.x) >> 5;
    int code = g_code[t];
    float s = 0.f;
    #pragma unroll
    for (int i = 0; i < 8; i++) {
        int e = lane + 32 * i;
        float d = Z[t * D_EMBV + e] - CB[code * D_EMBV + e];
        s += d * d;
    }
    #pragma unroll
    for (int o = 16; o > 0; o >>= 1) s += __shfl_xor_sync(0xffffffffu, s, o);
    if (lane == 0) atomicAdd(&g_loss[t >> 12], s);
}

__global__ void k_finish(float* __restrict__ out_commit, float* __restrict__ out_cb) {
    int i = threadIdx.x;
    if (i < N_BATCH) {
        float v = g_loss[i] * (1.0f / ((float)T_SEQ * (float)D_EMBV));
        out_commit[i] = v;
        out_cb[i] = v;
    }
}

// ---------------- launcher ----------------------------------------------------
extern "C" void kernel_launch(void* const* d_in, const int* in_sizes, int n_in,
                              void* d_out, int out_size) {
    const float* z_e    = (const float*)d_in[0];
    const float* cb     = (const float*)d_in[1];
    const float* w_down = (const float*)d_in[2];
    const float* w_up   = (const float*)d_in[3];

    float* out     = (float*)d_out;
    float* zq      = out;                                        // [BT, 512]
    float* zed     = out + (size_t)BT_TOK * D_INV;               // [BT, 256]
    float* codef   = out + (size_t)BT_TOK * (D_INV + D_EMBV);    // [BT]
    float* lcommit = codef + BT_TOK;                             // [16]
    float* lcb     = lcommit + N_BATCH;                          // [16]

    k_c2<<<(K_CODES + 255) / 256, 256>>>(cb);
    k_zero<<<1, 32>>>();
    k_down<<<dim3(BT_TOK / 64, D_EMBV / 64), 256>>>(z_e, w_down, zed);
    k_dist<<<BT_TOK / 64, 256>>>(zed, cb, codef);
    k_loss<<<BT_TOK / 8, 256>>>(zed, cb);
    k_up<<<dim3(BT_TOK / 64, D_INV / 64), 256>>>(cb, w_up, zq);
    k_finish<<<1, 32>>>(lcommit, lcb);
}